// round 5
// baseline (speedup 1.0000x reference)
#include <cuda_runtime.h>
#include <cuda_bf16.h>

#define N_NODES 50000
#define N_EDGES 800000
#define N_FEAT  512
#define N_HID   256
#define N_LAYER 4
#define N_CLASS 40
#define JK_DIM  (N_HID * N_LAYER)   // 1024

// ---------------- scratch (device globals; no allocation allowed) ----------
__device__ int   g_cnt[N_NODES];
__device__ int   g_off[N_NODES + 1];
__device__ int   g_cur[N_NODES];
__device__ int   g_bsum[16];
__device__ int   g_boff[16];
__device__ int   g_srt_src[N_EDGES];
__device__ float g_srt_coef[N_EDGES];
__device__ float g_dinv[N_NODES];
__device__ float g_selfn[N_NODES];
__device__ __align__(256) float g_hw [N_NODES * N_HID];            // layer0 only
__device__ __align__(256) float g_lin[N_NODES * N_HID];            // layer0 only
__device__ __align__(256) __nv_bfloat16 g_jkh[(size_t)N_NODES * JK_DIM];
__device__ __align__(256) __nv_bfloat16 g_jkl[(size_t)N_NODES * JK_DIM];
__device__ __align__(256) __nv_bfloat16 g_agh[(size_t)N_NODES * N_HID];
__device__ __align__(256) __nv_bfloat16 g_agl[(size_t)N_NODES * N_HID];
__device__ __align__(256) __nv_bfloat16 g_xh[(size_t)N_NODES * N_FEAT];
__device__ __align__(256) __nv_bfloat16 g_xl[(size_t)N_NODES * N_FEAT];
// layer0: [512n][512k] at offset 0; hidden layer l: [256n][512k] at HOFF(l)
__device__ __align__(256) __nv_bfloat16 g_Bh[4 * 512 * 512];
__device__ __align__(256) __nv_bfloat16 g_Bl[4 * 512 * 512];
__device__ __align__(256) __nv_bfloat16 g_Woh[64 * JK_DIM];
__device__ __align__(256) __nv_bfloat16 g_Wol[64 * JK_DIM];
#define HOFF(l) (512 * 512 + (l) * 256 * 512)

// ---------------- helpers ---------------------------------------------------
__device__ __forceinline__ unsigned su32(const void* p) {
    unsigned a;
    asm("{ .reg .u64 t; cvta.to.shared.u64 t, %1; cvt.u32.u64 %0, t; }"
        : "=r"(a) : "l"(p));
    return a;
}

__device__ __forceinline__ void cp16(unsigned d, const void* s, unsigned sz) {
    asm volatile("cp.async.cg.shared.global [%0], [%1], 16, %2;"
                 :: "r"(d), "l"(s), "r"(sz) : "memory");
}
#define CP_COMMIT asm volatile("cp.async.commit_group;" ::: "memory")
#define CP_WAIT1  asm volatile("cp.async.wait_group 1;" ::: "memory")
#define CP_WAIT0  asm volatile("cp.async.wait_group 0;" ::: "memory")

#define LDSM4(r, a) \
    asm volatile("ldmatrix.sync.aligned.m8n8.x4.shared.b16 {%0,%1,%2,%3}, [%4];" \
        : "=r"((r)[0]), "=r"((r)[1]), "=r"((r)[2]), "=r"((r)[3]) : "r"(a))

__device__ __forceinline__ void mma_bf16(float* c, const unsigned* a,
                                         unsigned b0, unsigned b1) {
    asm volatile("mma.sync.aligned.m16n8k16.row.col.f32.bf16.bf16.f32 "
        "{%0,%1,%2,%3}, {%4,%5,%6,%7}, {%8,%9}, {%0,%1,%2,%3};"
        : "+f"(c[0]), "+f"(c[1]), "+f"(c[2]), "+f"(c[3])
        : "r"(a[0]), "r"(a[1]), "r"(a[2]), "r"(a[3]), "r"(b0), "r"(b1));
}

__device__ __forceinline__ unsigned split_pack(float v0, float v1,
                                               unsigned& lo_out) {
    __nv_bfloat162 h, l;
    h.x = __float2bfloat16_rn(v0);
    h.y = __float2bfloat16_rn(v1);
    l.x = __float2bfloat16_rn(v0 - __bfloat162float(h.x));
    l.y = __float2bfloat16_rn(v1 - __bfloat162float(h.y));
    lo_out = *reinterpret_cast<unsigned*>(&l);
    return *reinterpret_cast<unsigned*>(&h);
}

// ---------------- preprocessing kernels -----------------------------------
__global__ void zero_cnt_kernel() {
    int i = blockIdx.x * blockDim.x + threadIdx.x;
    if (i < N_NODES) g_cnt[i] = 0;
}

__global__ void count_kernel(const int* __restrict__ dst) {
    int i = blockIdx.x * blockDim.x + threadIdx.x;
    if (i < N_EDGES) atomicAdd(&g_cnt[dst[i]], 1);
}

__global__ void dinv_kernel() {
    int i = blockIdx.x * blockDim.x + threadIdx.x;
    if (i < N_NODES) {
        float deg = (float)g_cnt[i] + 1.0f;
        float di  = rsqrtf(deg);
        g_dinv[i]  = di;
        g_selfn[i] = di * di;
    }
}

__global__ __launch_bounds__(1024)
void scan1_kernel() {
    __shared__ int sh[1024];
    int b = blockIdx.x, t = threadIdx.x;
    int idx = b * 4096 + t * 4;
    int s = 0;
    if (idx + 3 < N_NODES) {
        int4 v = *(const int4*)&g_cnt[idx];
        s = v.x + v.y + v.z + v.w;
    } else {
        for (int j = 0; j < 4; j++) if (idx + j < N_NODES) s += g_cnt[idx + j];
    }
    sh[t] = s;
    __syncthreads();
    for (int off = 512; off > 0; off >>= 1) {
        if (t < off) sh[t] += sh[t + off];
        __syncthreads();
    }
    if (t == 0) g_bsum[b] = sh[0];
}

__global__ void scan2_kernel(int nblk) {
    if (threadIdx.x == 0) {
        int acc = 0;
        for (int i = 0; i < nblk; i++) { g_boff[i] = acc; acc += g_bsum[i]; }
        g_off[N_NODES] = acc;
    }
}

__global__ __launch_bounds__(1024)
void scan3_kernel() {
    __shared__ int sh[1024];
    int b = blockIdx.x, t = threadIdx.x;
    int idx = b * 4096 + t * 4;
    int c0 = 0, c1 = 0, c2 = 0, c3 = 0;
    if (idx + 3 < N_NODES) {
        int4 v = *(const int4*)&g_cnt[idx];
        c0 = v.x; c1 = v.y; c2 = v.z; c3 = v.w;
    } else {
        if (idx + 0 < N_NODES) c0 = g_cnt[idx + 0];
        if (idx + 1 < N_NODES) c1 = g_cnt[idx + 1];
        if (idx + 2 < N_NODES) c2 = g_cnt[idx + 2];
        if (idx + 3 < N_NODES) c3 = g_cnt[idx + 3];
    }
    int s = c0 + c1 + c2 + c3;
    sh[t] = s;
    __syncthreads();
    for (int off = 1; off < 1024; off <<= 1) {
        int v = (t >= off) ? sh[t - off] : 0;
        __syncthreads();
        sh[t] += v;
        __syncthreads();
    }
    int excl = g_boff[b] + sh[t] - s;
    int4 ov = make_int4(excl, excl + c0, excl + c0 + c1, excl + c0 + c1 + c2);
    if (idx + 3 < N_NODES) {
        *(int4*)&g_off[idx] = ov;
        *(int4*)&g_cur[idx] = ov;
    } else {
        int o[4] = {ov.x, ov.y, ov.z, ov.w};
        for (int j = 0; j < 4; j++)
            if (idx + j < N_NODES) { g_off[idx + j] = o[j]; g_cur[idx + j] = o[j]; }
    }
}

__global__ void fill_kernel(const int* __restrict__ src, const int* __restrict__ dst) {
    int i = blockIdx.x * blockDim.x + threadIdx.x;
    if (i < N_EDGES) {
        int s = src[i], d = dst[i];
        int pos = atomicAdd(&g_cur[d], 1);
        g_srt_src[pos]  = s;
        g_srt_coef[pos] = g_dinv[s] * g_dinv[d];
    }
}

// ---------------- operand packing ------------------------------------------
__global__ void convert_x_kernel(const float* __restrict__ x) {
    size_t i = ((size_t)blockIdx.x * blockDim.x + threadIdx.x) * 4;
    if (i >= (size_t)N_NODES * N_FEAT) return;
    float4 v = *(const float4*)(x + i);
    unsigned l01, l23;
    unsigned h01 = split_pack(v.x, v.y, l01);
    unsigned h23 = split_pack(v.z, v.w, l23);
    *(uint2*)&g_xh[i] = make_uint2(h01, h23);
    *(uint2*)&g_xl[i] = make_uint2(l01, l23);
}

// layer0 B: [512n][512k]; n<256 gc cols, n>=256 lin cols
__global__ void pack_w0_kernel(const float* __restrict__ gcW0,
                               const float* __restrict__ linW0) {
    int i = blockIdx.x * blockDim.x + threadIdx.x;
    if (i >= 512 * 512) return;
    int n = i >> 9, k = i & 511;
    const float* W = (n < 256) ? gcW0 : linW0;
    float v = W[k * N_HID + (n & 255)];
    __nv_bfloat16 h = __float2bfloat16_rn(v);
    g_Bh[i] = h;
    g_Bl[i] = __float2bfloat16_rn(v - __bfloat162float(h));
}

// hidden B: per layer l (0..2): [256n][512k], k<256 -> convsW, k>=256 -> linsW
__global__ void pack_wh_kernel(const float* __restrict__ convsW,
                               const float* __restrict__ linsW) {
    int i = blockIdx.x * blockDim.x + threadIdx.x;
    if (i >= 3 * 256 * 512) return;
    int l = i / (256 * 512), rem = i % (256 * 512);
    int n = rem >> 9, k = rem & 511;
    float v;
    if (k < 256) v = convsW[l * N_HID * N_HID + k * N_HID + n];
    else         v = linsW [l * N_HID * N_HID + (k - 256) * N_HID + n];
    __nv_bfloat16 h = __float2bfloat16_rn(v);
    size_t o = HOFF(l) + (size_t)n * 512 + k;
    g_Bh[o] = h;
    g_Bl[o] = __float2bfloat16_rn(v - __bfloat162float(h));
}

// out_W packed n-major [64][1024], rows 40..63 zero
__global__ void pack_wo_kernel(const float* __restrict__ outW) {
    int i = blockIdx.x * blockDim.x + threadIdx.x;
    if (i >= 64 * JK_DIM) return;
    int n = i >> 10, k = i & 1023;
    float v = (n < N_CLASS) ? outW[k * N_CLASS + n] : 0.f;
    __nv_bfloat16 h = __float2bfloat16_rn(v);
    g_Woh[i] = h;
    g_Wol[i] = __float2bfloat16_rn(v - __bfloat162float(h));
}

// ---------------- layer-0 GEMM: C[M,512] = x[M,512] @ B0 -------------------
#define SM_BUF 40960
#define SM_ARR 10240

__global__ __launch_bounds__(256)
void gemm0_kernel(const __nv_bfloat16* __restrict__ Ah,
                  const __nv_bfloat16* __restrict__ Al,
                  float* __restrict__ Chw, float* __restrict__ Clin)
{
    extern __shared__ char smem[];
    const unsigned sbase = su32(smem);
    int tid  = threadIdx.x;
    int lane = tid & 31;
    int wid  = tid >> 5;
    int row0 = blockIdx.y * 128;
    int col0 = blockIdx.x * 128;
    int warpM = (wid >> 2) * 64;
    int warpN = (wid & 3) * 32;

    float acc[4][4][4];
    #pragma unroll
    for (int a = 0; a < 4; a++)
        #pragma unroll
        for (int b = 0; b < 4; b++)
            #pragma unroll
            for (int c = 0; c < 4; c++) acc[a][b][c] = 0.f;

    auto stage = [&](int buf, int k0) {
        #pragma unroll
        for (int t = 0; t < 8; t++) {
            int i = tid + t * 256;
            int arr = i >> 9, rem = i & 511, r = rem >> 2, c = rem & 3;
            unsigned dst = sbase + buf * SM_BUF + arr * SM_ARR + r * 80 + c * 16;
            const __nv_bfloat16* src;
            unsigned sz = 16;
            if (arr < 2) {
                int gr = row0 + r;
                if (gr >= N_NODES) { gr = N_NODES - 1; sz = 0; }
                src = (arr ? Al : Ah) + (size_t)gr * N_FEAT + k0 + c * 8;
            } else {
                src = ((arr == 2) ? g_Bh : g_Bl) + (size_t)(col0 + r) * 512 + k0 + c * 8;
            }
            cp16(dst, src, sz);
        }
    };

    stage(0, 0);
    CP_COMMIT;

    const int nch = N_FEAT >> 5;
    for (int ch = 0; ch < nch; ch++) {
        if (ch + 1 < nch) {
            stage((ch + 1) & 1, (ch + 1) << 5);
            CP_COMMIT;
            CP_WAIT1;
        } else {
            CP_WAIT0;
        }
        __syncthreads();

        unsigned abase = sbase + (ch & 1) * SM_BUF;
        unsigned bbase = abase + 2 * SM_ARR;
        int lrow = lane & 15;
        int lk16 = (lane >> 4) * 16;

        #pragma unroll
        for (int ks = 0; ks < 2; ks++) {
            unsigned ah[4][4], al[4][4];
            #pragma unroll
            for (int mt = 0; mt < 4; mt++) {
                unsigned adr = abase + (warpM + mt * 16 + lrow) * 80 + ks * 32 + lk16;
                LDSM4(ah[mt], adr);
                LDSM4(al[mt], adr + SM_ARR);
            }
            unsigned bh[2][4], bl[2][4];
            #pragma unroll
            for (int g = 0; g < 2; g++) {
                unsigned adr = bbase + (warpN + g * 16 + lrow) * 80 + ks * 32 + lk16;
                LDSM4(bh[g], adr);
                LDSM4(bl[g], adr + SM_ARR);
            }
            #pragma unroll
            for (int mt = 0; mt < 4; mt++)
                #pragma unroll
                for (int nt = 0; nt < 4; nt++) {
                    int g = nt >> 1, o = nt & 1;
                    mma_bf16(acc[mt][nt], ah[mt], bh[g][o], bh[g][2 + o]);
                    mma_bf16(acc[mt][nt], ah[mt], bl[g][o], bl[g][2 + o]);
                    mma_bf16(acc[mt][nt], al[mt], bh[g][o], bh[g][2 + o]);
                }
        }
        __syncthreads();
    }

    float* Cg = (col0 < 256) ? Chw : Clin;
    int cb = (col0 < 256) ? col0 : (col0 - 256);
    #pragma unroll
    for (int mt = 0; mt < 4; mt++)
        #pragma unroll
        for (int nt = 0; nt < 4; nt++) {
            int r = row0 + warpM + mt * 16 + (lane >> 2);
            int c = cb + warpN + nt * 8 + (lane & 3) * 2;
            if (r < N_NODES)
                *(float2*)&Cg[(size_t)r * N_HID + c] =
                    make_float2(acc[mt][nt][0], acc[mt][nt][1]);
            if (r + 8 < N_NODES)
                *(float2*)&Cg[(size_t)(r + 8) * N_HID + c] =
                    make_float2(acc[mt][nt][2], acc[mt][nt][3]);
        }
}

// ---------------- layer-0 post-aggregation (writes jk slot 0) --------------
__global__ __launch_bounds__(N_HID)
void agg_post_kernel(const float* __restrict__ hw, const float* __restrict__ lin,
                     const float* __restrict__ gcb, const float* __restrict__ linb)
{
    int n = blockIdx.x;
    int f = threadIdx.x;
    int beg = g_off[n], end = g_off[n + 1];

    float acc = 0.f;
    int e = beg;
    for (; e + 3 < end; e += 4) {
        int   s0 = g_srt_src[e],     s1 = g_srt_src[e + 1];
        int   s2 = g_srt_src[e + 2], s3 = g_srt_src[e + 3];
        float c0 = g_srt_coef[e],     c1 = g_srt_coef[e + 1];
        float c2 = g_srt_coef[e + 2], c3 = g_srt_coef[e + 3];
        acc += c0 * hw[s0 * N_HID + f];
        acc += c1 * hw[s1 * N_HID + f];
        acc += c2 * hw[s2 * N_HID + f];
        acc += c3 * hw[s3 * N_HID + f];
    }
    for (; e < end; e++)
        acc += g_srt_coef[e] * hw[g_srt_src[e] * N_HID + f];

    float r = acc + g_selfn[n] * hw[n * N_HID + f] + gcb[f]
              + lin[n * N_HID + f] + linb[f];
    float rm = fmaxf(r, 0.f);
    __nv_bfloat16 h = __float2bfloat16_rn(rm);
    size_t o = (size_t)n * JK_DIM + f;
    g_jkh[o] = h;
    g_jkl[o] = __float2bfloat16_rn(rm - __bfloat162float(h));
}

// ---------------- hidden-layer pre-aggregation: ag = S*h -------------------
// reads h = jk slot `slot` (hi+lo), writes g_agh/g_agl bf16 hi/lo
__global__ __launch_bounds__(N_HID)
void agg_pre_kernel(int slot)
{
    int n = blockIdx.x;
    int f = threadIdx.x;
    int so = slot * N_HID + f;
    int beg = g_off[n], end = g_off[n + 1];

    float acc = 0.f;
    int e = beg;
    for (; e + 3 < end; e += 4) {
        int   s0 = g_srt_src[e],     s1 = g_srt_src[e + 1];
        int   s2 = g_srt_src[e + 2], s3 = g_srt_src[e + 3];
        float c0 = g_srt_coef[e],     c1 = g_srt_coef[e + 1];
        float c2 = g_srt_coef[e + 2], c3 = g_srt_coef[e + 3];
        size_t o0 = (size_t)s0 * JK_DIM + so, o1 = (size_t)s1 * JK_DIM + so;
        size_t o2 = (size_t)s2 * JK_DIM + so, o3 = (size_t)s3 * JK_DIM + so;
        acc += c0 * (__bfloat162float(g_jkh[o0]) + __bfloat162float(g_jkl[o0]));
        acc += c1 * (__bfloat162float(g_jkh[o1]) + __bfloat162float(g_jkl[o1]));
        acc += c2 * (__bfloat162float(g_jkh[o2]) + __bfloat162float(g_jkl[o2]));
        acc += c3 * (__bfloat162float(g_jkh[o3]) + __bfloat162float(g_jkl[o3]));
    }
    for (; e < end; e++) {
        size_t o = (size_t)g_srt_src[e] * JK_DIM + so;
        acc += g_srt_coef[e] *
               (__bfloat162float(g_jkh[o]) + __bfloat162float(g_jkl[o]));
    }
    size_t on = (size_t)n * JK_DIM + so;
    acc += g_selfn[n] * (__bfloat162float(g_jkh[on]) + __bfloat162float(g_jkl[on]));

    __nv_bfloat16 h = __float2bfloat16_rn(acc);
    size_t o = (size_t)n * N_HID + f;
    g_agh[o] = h;
    g_agl[o] = __float2bfloat16_rn(acc - __bfloat162float(h));
}

// ---------------- hidden GEMM: jk_out = relu([ag|h] @ Bl + bias) -----------
// K=512 (0-255 from ag lda=256, 256-511 from jk slot lda=1024), N=256
__global__ __launch_bounds__(256)
void gemm_hidden_kernel(const __nv_bfloat16* __restrict__ Bh,
                        const __nv_bfloat16* __restrict__ Bl,
                        const float* __restrict__ bg,
                        const float* __restrict__ blin,
                        int slot_in, int slot_out)
{
    extern __shared__ char smem[];
    const unsigned sbase = su32(smem);
    int tid  = threadIdx.x;
    int lane = tid & 31;
    int wid  = tid >> 5;
    int row0 = blockIdx.y * 128;
    int col0 = blockIdx.x * 128;
    int warpM = (wid >> 2) * 64;
    int warpN = (wid & 3) * 32;

    const __nv_bfloat16* jh = g_jkh + slot_in * N_HID;
    const __nv_bfloat16* jl = g_jkl + slot_in * N_HID;

    float acc[4][4][4];
    #pragma unroll
    for (int a = 0; a < 4; a++)
        #pragma unroll
        for (int b = 0; b < 4; b++)
            #pragma unroll
            for (int c = 0; c < 4; c++) acc[a][b][c] = 0.f;

    auto stage = [&](int buf, int k0) {
        #pragma unroll
        for (int t = 0; t < 8; t++) {
            int i = tid + t * 256;
            int arr = i >> 9, rem = i & 511, r = rem >> 2, c = rem & 3;
            unsigned dst = sbase + buf * SM_BUF + arr * SM_ARR + r * 80 + c * 16;
            const __nv_bfloat16* src;
            unsigned sz = 16;
            if (arr < 2) {
                int gr = row0 + r;
                if (gr >= N_NODES) { gr = N_NODES - 1; sz = 0; }
                if (k0 < 256)
                    src = (arr ? g_agl : g_agh) + (size_t)gr * N_HID + k0 + c * 8;
                else
                    src = (arr ? jl : jh) + (size_t)gr * JK_DIM + (k0 - 256) + c * 8;
            } else {
                src = ((arr == 2) ? Bh : Bl) + (size_t)(col0 + r) * 512 + k0 + c * 8;
            }
            cp16(dst, src, sz);
        }
    };

    stage(0, 0);
    CP_COMMIT;

    const int nch = 512 >> 5;    // 16
    for (int ch = 0; ch < nch; ch++) {
        if (ch + 1 < nch) {
            stage((ch + 1) & 1, (ch + 1) << 5);
            CP_COMMIT;
            CP_WAIT1;
        } else {
            CP_WAIT0;
        }
        __syncthreads();

        unsigned abase = sbase + (ch & 1) * SM_BUF;
        unsigned bbase = abase + 2 * SM_ARR;
        int lrow = lane & 15;
        int lk16 = (lane >> 4) * 16;

        #pragma unroll
        for (int ks = 0; ks < 2; ks++) {
            unsigned ah[4][4], al[4][4];
            #pragma unroll
            for (int mt = 0; mt < 4; mt++) {
                unsigned adr = abase + (warpM + mt * 16 + lrow) * 80 + ks * 32 + lk16;
                LDSM4(ah[mt], adr);
                LDSM4(al[mt], adr + SM_ARR);
            }
            unsigned bh[2][4], bl2[2][4];
            #pragma unroll
            for (int g = 0; g < 2; g++) {
                unsigned adr = bbase + (warpN + g * 16 + lrow) * 80 + ks * 32 + lk16;
                LDSM4(bh[g], adr);
                LDSM4(bl2[g], adr + SM_ARR);
            }
            #pragma unroll
            for (int mt = 0; mt < 4; mt++)
                #pragma unroll
                for (int nt = 0; nt < 4; nt++) {
                    int g = nt >> 1, o = nt & 1;
                    mma_bf16(acc[mt][nt], ah[mt], bh[g][o],  bh[g][2 + o]);
                    mma_bf16(acc[mt][nt], ah[mt], bl2[g][o], bl2[g][2 + o]);
                    mma_bf16(acc[mt][nt], al[mt], bh[g][o],  bh[g][2 + o]);
                }
        }
        __syncthreads();
    }

    // epilogue: bias + relu + bf16 hi/lo split -> jk slot_out
    __nv_bfloat16* oh = g_jkh + slot_out * N_HID;
    __nv_bfloat16* ol = g_jkl + slot_out * N_HID;
    #pragma unroll
    for (int mt = 0; mt < 4; mt++)
        #pragma unroll
        for (int nt = 0; nt < 4; nt++) {
            int r = row0 + warpM + mt * 16 + (lane >> 2);
            int c = col0 + warpN + nt * 8 + (lane & 3) * 2;
            float b0 = bg[c] + blin[c];
            float b1 = bg[c + 1] + blin[c + 1];
            if (r < N_NODES) {
                float v0 = fmaxf(acc[mt][nt][0] + b0, 0.f);
                float v1 = fmaxf(acc[mt][nt][1] + b1, 0.f);
                unsigned lo, hi = split_pack(v0, v1, lo);
                *(unsigned*)&oh[(size_t)r * JK_DIM + c] = hi;
                *(unsigned*)&ol[(size_t)r * JK_DIM + c] = lo;
            }
            if (r + 8 < N_NODES) {
                float v0 = fmaxf(acc[mt][nt][2] + b0, 0.f);
                float v1 = fmaxf(acc[mt][nt][3] + b1, 0.f);
                unsigned lo, hi = split_pack(v0, v1, lo);
                *(unsigned*)&oh[(size_t)(r + 8) * JK_DIM + c] = hi;
                *(unsigned*)&ol[(size_t)(r + 8) * JK_DIM + c] = lo;
            }
        }
}

// ---------------- output GEMM via bf16x3 HMMA ------------------------------
#define OSM_A  10240
#define OSM_B  5120
#define OSM_BUF (2 * OSM_A + 2 * OSM_B)

__global__ __launch_bounds__(256)
void out_mma_kernel(const float* __restrict__ bias, float* __restrict__ out)
{
    extern __shared__ char smem[];
    const unsigned sbase = su32(smem);
    int tid  = threadIdx.x;
    int lane = tid & 31;
    int wid  = tid >> 5;
    int row0 = blockIdx.x * 128;

    float acc[5][4];
    #pragma unroll
    for (int a = 0; a < 5; a++)
        #pragma unroll
        for (int c = 0; c < 4; c++) acc[a][c] = 0.f;

    auto stage = [&](int buf, int k0) {
        #pragma unroll
        for (int t = 0; t < 6; t++) {
            int i = tid + t * 256;
            unsigned dst; const __nv_bfloat16* src; unsigned sz = 16;
            if (i < 1024) {
                int hl = i >> 9, rem = i & 511, r = rem >> 2, c = rem & 3;
                int gr = row0 + r;
                if (gr >= N_NODES) { gr = N_NODES - 1; sz = 0; }
                src = (hl ? g_jkl : g_jkh) + (size_t)gr * JK_DIM + k0 + c * 8;
                dst = sbase + buf * OSM_BUF + hl * OSM_A + r * 80 + c * 16;
            } else {
                int j = i - 1024;
                int hl = j >> 8, rem = j & 255, r = rem >> 2, c = rem & 3;
                src = (hl ? g_Wol : g_Woh) + (size_t)r * JK_DIM + k0 + c * 8;
                dst = sbase + buf * OSM_BUF + 2 * OSM_A + hl * OSM_B + r * 80 + c * 16;
            }
            cp16(dst, src, sz);
        }
    };

    stage(0, 0);
    CP_COMMIT;

    const int nch = JK_DIM / 32;
    for (int ch = 0; ch < nch; ch++) {
        if (ch + 1 < nch) {
            stage((ch + 1) & 1, (ch + 1) * 32);
            CP_COMMIT;
            CP_WAIT1;
        } else {
            CP_WAIT0;
        }
        __syncthreads();

        unsigned abase = sbase + (ch & 1) * OSM_BUF;
        unsigned bbase = abase + 2 * OSM_A;
        int lrow = lane & 15;
        int lk16 = (lane >> 4) * 16;

        #pragma unroll
        for (int ks = 0; ks < 2; ks++) {
            unsigned ah[4], al[4];
            unsigned adr = abase + (wid * 16 + lrow) * 80 + ks * 32 + lk16;
            LDSM4(ah, adr);
            LDSM4(al, adr + OSM_A);
            unsigned bh[3][4], bl[3][4];
            #pragma unroll
            for (int g = 0; g < 3; g++) {
                unsigned badr = bbase + (g * 16 + lrow) * 80 + ks * 32 + lk16;
                LDSM4(bh[g], badr);
                LDSM4(bl[g], badr + OSM_B);
            }
            #pragma unroll
            for (int nt = 0; nt < 5; nt++) {
                int g = nt >> 1, o = nt & 1;
                mma_bf16(acc[nt], ah, bh[g][o], bh[g][2 + o]);
                mma_bf16(acc[nt], ah, bl[g][o], bl[g][2 + o]);
                mma_bf16(acc[nt], al, bh[g][o], bh[g][2 + o]);
            }
        }
        __syncthreads();
    }

    #pragma unroll
    for (int nt = 0; nt < 5; nt++) {
        int c = nt * 8 + (lane & 3) * 2;
        float2 bv = make_float2(bias[c], bias[c + 1]);
        int r = row0 + wid * 16 + (lane >> 2);
        if (r < N_NODES)
            *(float2*)&out[(size_t)r * N_CLASS + c] =
                make_float2(acc[nt][0] + bv.x, acc[nt][1] + bv.y);
        if (r + 8 < N_NODES)
            *(float2*)&out[(size_t)(r + 8) * N_CLASS + c] =
                make_float2(acc[nt][2] + bv.x, acc[nt][3] + bv.y);
    }
}

// ---------------- launch ---------------------------------------------------
extern "C" void kernel_launch(void* const* d_in, const int* in_sizes, int n_in,
                              void* d_out, int out_size)
{
    const float* x        = (const float*)d_in[0];
    const int*   edge     = (const int*)  d_in[1];
    const float* in_gc_W  = (const float*)d_in[2];
    const float* in_gc_b  = (const float*)d_in[3];
    const float* in_lin_W = (const float*)d_in[4];
    const float* in_lin_b = (const float*)d_in[5];
    const float* convs_W  = (const float*)d_in[6];
    const float* convs_b  = (const float*)d_in[7];
    const float* lins_W   = (const float*)d_in[8];
    const float* lins_b   = (const float*)d_in[9];
    const float* out_W    = (const float*)d_in[10];
    const float* out_b    = (const float*)d_in[11];
    float*       out      = (float*)d_out;

    const int* src = edge;
    const int* dst = edge + N_EDGES;

    float *p_hw, *p_lin;
    cudaGetSymbolAddress((void**)&p_hw,  g_hw);
    cudaGetSymbolAddress((void**)&p_lin, g_lin);
    __nv_bfloat16 *p_xh, *p_xl, *p_Bh, *p_Bl;
    cudaGetSymbolAddress((void**)&p_xh,  g_xh);
    cudaGetSymbolAddress((void**)&p_xl,  g_xl);
    cudaGetSymbolAddress((void**)&p_Bh,  g_Bh);
    cudaGetSymbolAddress((void**)&p_Bl,  g_Bl);

    cudaFuncSetAttribute(gemm0_kernel,
                         cudaFuncAttributeMaxDynamicSharedMemorySize, 2 * SM_BUF);
    cudaFuncSetAttribute(gemm_hidden_kernel,
                         cudaFuncAttributeMaxDynamicSharedMemorySize, 2 * SM_BUF);
    cudaFuncSetAttribute(out_mma_kernel,
                         cudaFuncAttributeMaxDynamicSharedMemorySize, 2 * OSM_BUF);

    // order: my#4 (global idx 5 under ncu -s 5) = count_kernel
    zero_cnt_kernel<<<(N_NODES + 255) / 256, 256>>>();
    convert_x_kernel<<<(N_NODES * N_FEAT / 4 + 255) / 256, 256>>>(x);
    pack_w0_kernel<<<(512 * 512 + 255) / 256, 256>>>(in_gc_W, in_lin_W);
    count_kernel<<<(N_EDGES + 255) / 256, 256>>>(dst);          // <- profiled
    pack_wh_kernel<<<(3 * 256 * 512 + 255) / 256, 256>>>(convs_W, lins_W);
    pack_wo_kernel<<<(64 * JK_DIM + 255) / 256, 256>>>(out_W);
    dinv_kernel<<<(N_NODES + 255) / 256, 256>>>();
    scan1_kernel<<<13, 1024>>>();
    scan2_kernel<<<1, 32>>>(13);
    scan3_kernel<<<13, 1024>>>();
    fill_kernel<<<(N_EDGES + 255) / 256, 256>>>(src, dst);

    dim3 g0grid(4, (N_NODES + 127) / 128);
    gemm0_kernel<<<g0grid, 256, 2 * SM_BUF>>>(p_xh, p_xl, p_hw, p_lin);
    agg_post_kernel<<<N_NODES, N_HID>>>(p_hw, p_lin, in_gc_b, in_lin_b);

    dim3 ghgrid(2, (N_NODES + 127) / 128);
    for (int i = 0; i < N_LAYER - 1; i++) {
        agg_pre_kernel<<<N_NODES, N_HID>>>(i);
        gemm_hidden_kernel<<<ghgrid, 256, 2 * SM_BUF>>>(
            p_Bh + HOFF(i), p_Bl + HOFF(i),
            convs_b + i * N_HID, lins_b + i * N_HID, i, i + 1);
    }

    out_mma_kernel<<<(N_NODES + 127) / 128, 256, 2 * OSM_BUF>>>(out_b, out);
}

// round 6
// speedup vs baseline: 1.4267x; 1.4267x over previous
#include <cuda_runtime.h>
#include <cuda_bf16.h>

#define N_NODES 50000
#define N_EDGES 800000
#define N_FEAT  512
#define N_HID   256
#define N_LAYER 4
#define N_CLASS 40
#define JK_DIM  (N_HID * N_LAYER)   // 1024

// ---------------- scratch (device globals; no allocation allowed) ----------
__device__ int   g_cnt[N_NODES];
__device__ int   g_off[N_NODES + 1];
__device__ int   g_cur[N_NODES];
__device__ int   g_bsum[16];
__device__ int   g_boff[16];
__device__ __align__(16) int2 g_edge[N_EDGES];      // {src, coef bits}
__device__ float g_dinv[N_NODES];
__device__ float g_selfn[N_NODES];
__device__ __align__(256) float g_hw [N_NODES * N_HID];            // 51.2 MB
__device__ __align__(256) float g_lin[N_NODES * N_HID];            // 51.2 MB
__device__ __align__(256) __nv_bfloat16 g_jkh[(size_t)N_NODES * JK_DIM];
__device__ __align__(256) __nv_bfloat16 g_jkl[(size_t)N_NODES * JK_DIM];
__device__ __align__(256) __nv_bfloat16 g_xh[(size_t)N_NODES * N_FEAT];
__device__ __align__(256) __nv_bfloat16 g_xl[(size_t)N_NODES * N_FEAT];
// per layer l: [512n][512k] at l*512*512 (hidden layers use k<256)
__device__ __align__(256) __nv_bfloat16 g_Bh[4 * 512 * 512];
__device__ __align__(256) __nv_bfloat16 g_Bl[4 * 512 * 512];
__device__ __align__(256) __nv_bfloat16 g_Woh[64 * JK_DIM];
__device__ __align__(256) __nv_bfloat16 g_Wol[64 * JK_DIM];

// ---------------- helpers ---------------------------------------------------
__device__ __forceinline__ unsigned su32(const void* p) {
    unsigned a;
    asm("{ .reg .u64 t; cvta.to.shared.u64 t, %1; cvt.u32.u64 %0, t; }"
        : "=r"(a) : "l"(p));
    return a;
}

__device__ __forceinline__ void cp16(unsigned d, const void* s, unsigned sz) {
    asm volatile("cp.async.cg.shared.global [%0], [%1], 16, %2;"
                 :: "r"(d), "l"(s), "r"(sz) : "memory");
}
#define CP_COMMIT asm volatile("cp.async.commit_group;" ::: "memory")
#define CP_WAIT0  asm volatile("cp.async.wait_group 0;" ::: "memory")

#define LDSM4(r, a) \
    asm volatile("ldmatrix.sync.aligned.m8n8.x4.shared.b16 {%0,%1,%2,%3}, [%4];" \
        : "=r"((r)[0]), "=r"((r)[1]), "=r"((r)[2]), "=r"((r)[3]) : "r"(a))

__device__ __forceinline__ void mma_bf16(float* c, const unsigned* a,
                                         unsigned b0, unsigned b1) {
    asm volatile("mma.sync.aligned.m16n8k16.row.col.f32.bf16.bf16.f32 "
        "{%0,%1,%2,%3}, {%4,%5,%6,%7}, {%8,%9}, {%0,%1,%2,%3};"
        : "+f"(c[0]), "+f"(c[1]), "+f"(c[2]), "+f"(c[3])
        : "r"(a[0]), "r"(a[1]), "r"(a[2]), "r"(a[3]), "r"(b0), "r"(b1));
}

__device__ __forceinline__ unsigned split_pack(float v0, float v1,
                                               unsigned& lo_out) {
    __nv_bfloat162 h, l;
    h.x = __float2bfloat16_rn(v0);
    h.y = __float2bfloat16_rn(v1);
    l.x = __float2bfloat16_rn(v0 - __bfloat162float(h.x));
    l.y = __float2bfloat16_rn(v1 - __bfloat162float(h.y));
    lo_out = *reinterpret_cast<unsigned*>(&l);
    return *reinterpret_cast<unsigned*>(&h);
}

// ---------------- preprocessing kernels -----------------------------------
__global__ void zero_cnt_kernel() {
    int i = blockIdx.x * blockDim.x + threadIdx.x;
    if (i < N_NODES) g_cnt[i] = 0;
}

__global__ void count_kernel(const int* __restrict__ dst) {
    int i = blockIdx.x * blockDim.x + threadIdx.x;
    if (i < N_EDGES) atomicAdd(&g_cnt[dst[i]], 1);
}

__global__ void dinv_kernel() {
    int i = blockIdx.x * blockDim.x + threadIdx.x;
    if (i < N_NODES) {
        float deg = (float)g_cnt[i] + 1.0f;
        float di  = rsqrtf(deg);
        g_dinv[i]  = di;
        g_selfn[i] = di * di;
    }
}

__global__ __launch_bounds__(1024)
void scan1_kernel() {
    __shared__ int sh[1024];
    int b = blockIdx.x, t = threadIdx.x;
    int idx = b * 4096 + t * 4;
    int s = 0;
    if (idx + 3 < N_NODES) {
        int4 v = *(const int4*)&g_cnt[idx];
        s = v.x + v.y + v.z + v.w;
    } else {
        for (int j = 0; j < 4; j++) if (idx + j < N_NODES) s += g_cnt[idx + j];
    }
    sh[t] = s;
    __syncthreads();
    for (int off = 512; off > 0; off >>= 1) {
        if (t < off) sh[t] += sh[t + off];
        __syncthreads();
    }
    if (t == 0) g_bsum[b] = sh[0];
}

__global__ void scan2_kernel(int nblk) {
    if (threadIdx.x == 0) {
        int acc = 0;
        for (int i = 0; i < nblk; i++) { g_boff[i] = acc; acc += g_bsum[i]; }
        g_off[N_NODES] = acc;
    }
}

__global__ __launch_bounds__(1024)
void scan3_kernel() {
    __shared__ int sh[1024];
    int b = blockIdx.x, t = threadIdx.x;
    int idx = b * 4096 + t * 4;
    int c0 = 0, c1 = 0, c2 = 0, c3 = 0;
    if (idx + 3 < N_NODES) {
        int4 v = *(const int4*)&g_cnt[idx];
        c0 = v.x; c1 = v.y; c2 = v.z; c3 = v.w;
    } else {
        if (idx + 0 < N_NODES) c0 = g_cnt[idx + 0];
        if (idx + 1 < N_NODES) c1 = g_cnt[idx + 1];
        if (idx + 2 < N_NODES) c2 = g_cnt[idx + 2];
        if (idx + 3 < N_NODES) c3 = g_cnt[idx + 3];
    }
    int s = c0 + c1 + c2 + c3;
    sh[t] = s;
    __syncthreads();
    for (int off = 1; off < 1024; off <<= 1) {
        int v = (t >= off) ? sh[t - off] : 0;
        __syncthreads();
        sh[t] += v;
        __syncthreads();
    }
    int excl = g_boff[b] + sh[t] - s;
    int4 ov = make_int4(excl, excl + c0, excl + c0 + c1, excl + c0 + c1 + c2);
    if (idx + 3 < N_NODES) {
        *(int4*)&g_off[idx] = ov;
        *(int4*)&g_cur[idx] = ov;
    } else {
        int o[4] = {ov.x, ov.y, ov.z, ov.w};
        for (int j = 0; j < 4; j++)
            if (idx + j < N_NODES) { g_off[idx + j] = o[j]; g_cur[idx + j] = o[j]; }
    }
}

__global__ void fill_kernel(const int* __restrict__ src, const int* __restrict__ dst) {
    int i = blockIdx.x * blockDim.x + threadIdx.x;
    if (i < N_EDGES) {
        int s = src[i], d = dst[i];
        int pos = atomicAdd(&g_cur[d], 1);
        g_edge[pos] = make_int2(s, __float_as_int(g_dinv[s] * g_dinv[d]));
    }
}

// ---------------- operand packing ------------------------------------------
__global__ void convert_x_kernel(const float* __restrict__ x) {
    size_t i = ((size_t)blockIdx.x * blockDim.x + threadIdx.x) * 4;
    if (i >= (size_t)N_NODES * N_FEAT) return;
    float4 v = *(const float4*)(x + i);
    unsigned l01, l23;
    unsigned h01 = split_pack(v.x, v.y, l01);
    unsigned h23 = split_pack(v.z, v.w, l23);
    *(uint2*)&g_xh[i] = make_uint2(h01, h23);
    *(uint2*)&g_xl[i] = make_uint2(l01, l23);
}

// B slabs: layer l n-major [512][512]; n<256 gc cols, n>=256 lin cols
__global__ void pack_w_kernel(const float* __restrict__ gcW0,
                              const float* __restrict__ linW0,
                              const float* __restrict__ convsW,
                              const float* __restrict__ linsW) {
    int i = blockIdx.x * blockDim.x + threadIdx.x;
    if (i >= 4 * 512 * 512) return;
    int l = i >> 18, rem = i & 262143, n = rem >> 9, k = rem & 511;
    int Kl = l ? N_HID : N_FEAT;
    if (k >= Kl) return;
    const float* W;
    if (l == 0) W = (n < 256) ? gcW0 : linW0;
    else        W = ((n < 256) ? convsW : linsW) + (l - 1) * N_HID * N_HID;
    float v = W[k * N_HID + (n & 255)];
    __nv_bfloat16 h = __float2bfloat16_rn(v);
    g_Bh[i] = h;
    g_Bl[i] = __float2bfloat16_rn(v - __bfloat162float(h));
}

// out_W packed n-major [64][1024], rows 40..63 zero
__global__ void pack_wo_kernel(const float* __restrict__ outW) {
    int i = blockIdx.x * blockDim.x + threadIdx.x;
    if (i >= 64 * JK_DIM) return;
    int n = i >> 10, k = i & 1023;
    float v = (n < N_CLASS) ? outW[k * N_CLASS + n] : 0.f;
    __nv_bfloat16 h = __float2bfloat16_rn(v);
    g_Woh[i] = h;
    g_Wol[i] = __float2bfloat16_rn(v - __bfloat162float(h));
}

// ---------------- bf16x3 GEMM: C[M,512] = A[M,K] @ B[K,512] ---------------
#define SM_BUF 40960
#define SM_ARR 10240

__global__ __launch_bounds__(256)
void gemm_bf16x3_kernel(const __nv_bfloat16* __restrict__ Ah,
                        const __nv_bfloat16* __restrict__ Al,
                        const __nv_bfloat16* __restrict__ Bh,
                        const __nv_bfloat16* __restrict__ Bl,
                        float* __restrict__ Chw, float* __restrict__ Clin,
                        int M, int K, int lda)
{
    extern __shared__ char smem[];
    const unsigned sbase = su32(smem);
    int tid  = threadIdx.x;
    int lane = tid & 31;
    int wid  = tid >> 5;
    int row0 = blockIdx.y * 128;
    int col0 = blockIdx.x * 128;
    int warpM = (wid >> 2) * 64;
    int warpN = (wid & 3) * 32;

    float acc[4][4][4];
    #pragma unroll
    for (int a = 0; a < 4; a++)
        #pragma unroll
        for (int b = 0; b < 4; b++)
            #pragma unroll
            for (int c = 0; c < 4; c++) acc[a][b][c] = 0.f;

    auto stage = [&](int buf, int k0) {
        #pragma unroll
        for (int t = 0; t < 8; t++) {
            int i = tid + t * 256;
            int arr = i >> 9, rem = i & 511, r = rem >> 2, c = rem & 3;
            unsigned dst = sbase + buf * SM_BUF + arr * SM_ARR + r * 80 + c * 16;
            const __nv_bfloat16* src;
            unsigned sz = 16;
            if (arr < 2) {
                int gr = row0 + r;
                if (gr >= M) { gr = M - 1; sz = 0; }
                src = (arr ? Al : Ah) + (size_t)gr * lda + k0 + c * 8;
            } else {
                src = ((arr == 2) ? Bh : Bl) + (size_t)(col0 + r) * 512 + k0 + c * 8;
            }
            cp16(dst, src, sz);
        }
    };

    stage(0, 0);
    CP_COMMIT;

    const int nch = K >> 5;
    for (int ch = 0; ch < nch; ch++) {
        CP_WAIT0;
        __syncthreads();
        if (ch + 1 < nch) {
            stage((ch + 1) & 1, (ch + 1) << 5);
            CP_COMMIT;
        }

        unsigned abase = sbase + (ch & 1) * SM_BUF;
        unsigned bbase = abase + 2 * SM_ARR;
        int lrow = lane & 15;
        int lk16 = (lane >> 4) * 16;

        #pragma unroll
        for (int ks = 0; ks < 2; ks++) {
            unsigned ah[4][4], al[4][4];
            #pragma unroll
            for (int mt = 0; mt < 4; mt++) {
                unsigned adr = abase + (warpM + mt * 16 + lrow) * 80 + ks * 32 + lk16;
                LDSM4(ah[mt], adr);
                LDSM4(al[mt], adr + SM_ARR);
            }
            unsigned bh[2][4], bl[2][4];
            #pragma unroll
            for (int g = 0; g < 2; g++) {
                unsigned adr = bbase + (warpN + g * 16 + lrow) * 80 + ks * 32 + lk16;
                LDSM4(bh[g], adr);
                LDSM4(bl[g], adr + SM_ARR);
            }
            #pragma unroll
            for (int mt = 0; mt < 4; mt++)
                #pragma unroll
                for (int nt = 0; nt < 4; nt++) {
                    int g = nt >> 1, o = nt & 1;
                    mma_bf16(acc[mt][nt], ah[mt], bh[g][o], bh[g][2 + o]);
                    mma_bf16(acc[mt][nt], ah[mt], bl[g][o], bl[g][2 + o]);
                    mma_bf16(acc[mt][nt], al[mt], bh[g][o], bh[g][2 + o]);
                }
        }
    }

    float* Cg = (col0 < 256) ? Chw : Clin;
    int cb = (col0 < 256) ? col0 : (col0 - 256);
    #pragma unroll
    for (int mt = 0; mt < 4; mt++)
        #pragma unroll
        for (int nt = 0; nt < 4; nt++) {
            int r = row0 + warpM + mt * 16 + (lane >> 2);
            int c = cb + warpN + nt * 8 + (lane & 3) * 2;
            if (r < M)
                *(float2*)&Cg[(size_t)r * N_HID + c] =
                    make_float2(acc[mt][nt][0], acc[mt][nt][1]);
            if (r + 8 < M)
                *(float2*)&Cg[(size_t)(r + 8) * N_HID + c] =
                    make_float2(acc[mt][nt][2], acc[mt][nt][3]);
        }
}

// ---------------- fused GCN aggregation epilogue ---------------------------
// 64 threads/block, thread owns 4 feats (float4); int2 edge records
__global__ __launch_bounds__(64)
void agg_kernel(const float* __restrict__ hw, const float* __restrict__ lin,
                const float* __restrict__ gcb, const float* __restrict__ linb,
                int slot)
{
    int n  = blockIdx.x;
    int f4 = threadIdx.x * 4;
    int beg = g_off[n], end = g_off[n + 1];

    float4 acc = make_float4(0.f, 0.f, 0.f, 0.f);
    int e = beg;
    for (; e + 3 < end; e += 4) {
        int2 p0 = g_edge[e],     p1 = g_edge[e + 1];
        int2 p2 = g_edge[e + 2], p3 = g_edge[e + 3];
        float4 v0 = *(const float4*)&hw[(size_t)p0.x * N_HID + f4];
        float4 v1 = *(const float4*)&hw[(size_t)p1.x * N_HID + f4];
        float4 v2 = *(const float4*)&hw[(size_t)p2.x * N_HID + f4];
        float4 v3 = *(const float4*)&hw[(size_t)p3.x * N_HID + f4];
        float c0 = __int_as_float(p0.y), c1 = __int_as_float(p1.y);
        float c2 = __int_as_float(p2.y), c3 = __int_as_float(p3.y);
        acc.x += c0 * v0.x + c1 * v1.x + c2 * v2.x + c3 * v3.x;
        acc.y += c0 * v0.y + c1 * v1.y + c2 * v2.y + c3 * v3.y;
        acc.z += c0 * v0.z + c1 * v1.z + c2 * v2.z + c3 * v3.z;
        acc.w += c0 * v0.w + c1 * v1.w + c2 * v2.w + c3 * v3.w;
    }
    for (; e < end; e++) {
        int2 p = g_edge[e];
        float4 v = *(const float4*)&hw[(size_t)p.x * N_HID + f4];
        float c = __int_as_float(p.y);
        acc.x += c * v.x; acc.y += c * v.y;
        acc.z += c * v.z; acc.w += c * v.w;
    }

    float  sn = g_selfn[n];
    float4 vs = *(const float4*)&hw[(size_t)n * N_HID + f4];
    float4 vl = *(const float4*)&lin[(size_t)n * N_HID + f4];
    float4 bg = *(const float4*)&gcb[f4];
    float4 bl = *(const float4*)&linb[f4];

    float r0 = fmaxf(acc.x + sn * vs.x + bg.x + vl.x + bl.x, 0.f);
    float r1 = fmaxf(acc.y + sn * vs.y + bg.y + vl.y + bl.y, 0.f);
    float r2 = fmaxf(acc.z + sn * vs.z + bg.z + vl.z + bl.z, 0.f);
    float r3 = fmaxf(acc.w + sn * vs.w + bg.w + vl.w + bl.w, 0.f);

    unsigned l01, l23;
    unsigned h01 = split_pack(r0, r1, l01);
    unsigned h23 = split_pack(r2, r3, l23);
    size_t o = (size_t)n * JK_DIM + slot * N_HID + f4;
    *(uint2*)&g_jkh[o] = make_uint2(h01, h23);
    *(uint2*)&g_jkl[o] = make_uint2(l01, l23);
}

// ---------------- output GEMM via bf16x3 HMMA ------------------------------
#define OSM_A  10240
#define OSM_B  5120
#define OSM_BUF (2 * OSM_A + 2 * OSM_B)

__global__ __launch_bounds__(256)
void out_mma_kernel(const float* __restrict__ bias, float* __restrict__ out)
{
    extern __shared__ char smem[];
    const unsigned sbase = su32(smem);
    int tid  = threadIdx.x;
    int lane = tid & 31;
    int wid  = tid >> 5;
    int row0 = blockIdx.x * 128;

    float acc[5][4];
    #pragma unroll
    for (int a = 0; a < 5; a++)
        #pragma unroll
        for (int c = 0; c < 4; c++) acc[a][c] = 0.f;

    auto stage = [&](int buf, int k0) {
        #pragma unroll
        for (int t = 0; t < 6; t++) {
            int i = tid + t * 256;
            unsigned dst; const __nv_bfloat16* src; unsigned sz = 16;
            if (i < 1024) {
                int hl = i >> 9, rem = i & 511, r = rem >> 2, c = rem & 3;
                int gr = row0 + r;
                if (gr >= N_NODES) { gr = N_NODES - 1; sz = 0; }
                src = (hl ? g_jkl : g_jkh) + (size_t)gr * JK_DIM + k0 + c * 8;
                dst = sbase + buf * OSM_BUF + hl * OSM_A + r * 80 + c * 16;
            } else {
                int j = i - 1024;
                int hl = j >> 8, rem = j & 255, r = rem >> 2, c = rem & 3;
                src = (hl ? g_Wol : g_Woh) + (size_t)r * JK_DIM + k0 + c * 8;
                dst = sbase + buf * OSM_BUF + 2 * OSM_A + hl * OSM_B + r * 80 + c * 16;
            }
            cp16(dst, src, sz);
        }
    };

    stage(0, 0);
    CP_COMMIT;

    const int nch = JK_DIM / 32;
    for (int ch = 0; ch < nch; ch++) {
        CP_WAIT0;
        __syncthreads();
        if (ch + 1 < nch) {
            stage((ch + 1) & 1, (ch + 1) * 32);
            CP_COMMIT;
        }

        unsigned abase = sbase + (ch & 1) * OSM_BUF;
        unsigned bbase = abase + 2 * OSM_A;
        int lrow = lane & 15;
        int lk16 = (lane >> 4) * 16;

        #pragma unroll
        for (int ks = 0; ks < 2; ks++) {
            unsigned ah[4], al[4];
            unsigned adr = abase + (wid * 16 + lrow) * 80 + ks * 32 + lk16;
            LDSM4(ah, adr);
            LDSM4(al, adr + OSM_A);
            unsigned bh[3][4], bl[3][4];
            #pragma unroll
            for (int g = 0; g < 3; g++) {
                unsigned badr = bbase + (g * 16 + lrow) * 80 + ks * 32 + lk16;
                LDSM4(bh[g], badr);
                LDSM4(bl[g], badr + OSM_B);
            }
            #pragma unroll
            for (int nt = 0; nt < 5; nt++) {
                int g = nt >> 1, o = nt & 1;
                mma_bf16(acc[nt], ah, bh[g][o], bh[g][2 + o]);
                mma_bf16(acc[nt], ah, bl[g][o], bl[g][2 + o]);
                mma_bf16(acc[nt], al, bh[g][o], bh[g][2 + o]);
            }
        }
    }

    #pragma unroll
    for (int nt = 0; nt < 5; nt++) {
        int c = nt * 8 + (lane & 3) * 2;
        float2 bv = make_float2(bias[c], bias[c + 1]);
        int r = row0 + wid * 16 + (lane >> 2);
        if (r < N_NODES)
            *(float2*)&out[(size_t)r * N_CLASS + c] =
                make_float2(acc[nt][0] + bv.x, acc[nt][1] + bv.y);
        if (r + 8 < N_NODES)
            *(float2*)&out[(size_t)(r + 8) * N_CLASS + c] =
                make_float2(acc[nt][2] + bv.x, acc[nt][3] + bv.y);
    }
}

// ---------------- launch ---------------------------------------------------
extern "C" void kernel_launch(void* const* d_in, const int* in_sizes, int n_in,
                              void* d_out, int out_size)
{
    const float* x        = (const float*)d_in[0];
    const int*   edge     = (const int*)  d_in[1];
    const float* in_gc_W  = (const float*)d_in[2];
    const float* in_gc_b  = (const float*)d_in[3];
    const float* in_lin_W = (const float*)d_in[4];
    const float* in_lin_b = (const float*)d_in[5];
    const float* convs_W  = (const float*)d_in[6];
    const float* convs_b  = (const float*)d_in[7];
    const float* lins_W   = (const float*)d_in[8];
    const float* lins_b   = (const float*)d_in[9];
    const float* out_W    = (const float*)d_in[10];
    const float* out_b    = (const float*)d_in[11];
    float*       out      = (float*)d_out;

    const int* src = edge;
    const int* dst = edge + N_EDGES;

    float *p_hw, *p_lin;
    cudaGetSymbolAddress((void**)&p_hw,  g_hw);
    cudaGetSymbolAddress((void**)&p_lin, g_lin);
    __nv_bfloat16 *p_xh, *p_xl, *p_jkh, *p_jkl, *p_Bh, *p_Bl;
    cudaGetSymbolAddress((void**)&p_xh,  g_xh);
    cudaGetSymbolAddress((void**)&p_xl,  g_xl);
    cudaGetSymbolAddress((void**)&p_jkh, g_jkh);
    cudaGetSymbolAddress((void**)&p_jkl, g_jkl);
    cudaGetSymbolAddress((void**)&p_Bh,  g_Bh);
    cudaGetSymbolAddress((void**)&p_Bl,  g_Bl);

    cudaFuncSetAttribute(gemm_bf16x3_kernel,
                         cudaFuncAttributeMaxDynamicSharedMemorySize, 2 * SM_BUF);
    cudaFuncSetAttribute(out_mma_kernel,
                         cudaFuncAttributeMaxDynamicSharedMemorySize, 2 * OSM_BUF);

    dim3 ggrid(4, (N_NODES + 127) / 128);

    // order: my #4 (profiled under ncu -s 5) = gemm layer 0
    convert_x_kernel<<<(N_NODES * N_FEAT / 4 + 255) / 256, 256>>>(x);
    pack_w_kernel<<<(4 * 512 * 512 + 255) / 256, 256>>>(in_gc_W, in_lin_W,
                                                        convs_W, lins_W);
    zero_cnt_kernel<<<(N_NODES + 255) / 256, 256>>>();
    gemm_bf16x3_kernel<<<ggrid, 256, 2 * SM_BUF>>>(      // <- profiled
        p_xh, p_xl, p_Bh, p_Bl, p_hw, p_lin, N_NODES, N_FEAT, N_FEAT);
    pack_wo_kernel<<<(64 * JK_DIM + 255) / 256, 256>>>(out_W);
    count_kernel<<<(N_EDGES + 255) / 256, 256>>>(dst);
    dinv_kernel<<<(N_NODES + 255) / 256, 256>>>();
    scan1_kernel<<<13, 1024>>>();
    scan2_kernel<<<1, 32>>>(13);
    scan3_kernel<<<13, 1024>>>();
    fill_kernel<<<(N_EDGES + 255) / 256, 256>>>(src, dst);

    agg_kernel<<<N_NODES, 64>>>(p_hw, p_lin, in_gc_b, in_lin_b, 0);

    for (int i = 0; i < N_LAYER - 1; i++) {
        gemm_bf16x3_kernel<<<ggrid, 256, 2 * SM_BUF>>>(
            p_jkh + i * N_HID, p_jkl + i * N_HID,
            p_Bh + (size_t)(i + 1) * 512 * 512,
            p_Bl + (size_t)(i + 1) * 512 * 512,
            p_hw, p_lin, N_NODES, N_HID, JK_DIM);
        agg_kernel<<<N_NODES, 64>>>(p_hw, p_lin,
                                    convs_b + i * N_HID, lins_b + i * N_HID,
                                    i + 1);
    }

    out_mma_kernel<<<(N_NODES + 127) / 128, 256, 2 * OSM_BUF>>>(out_b, out);
}